// round 11
// baseline (speedup 1.0000x reference)
#include <cuda_runtime.h>
#include <cuda_fp16.h>
#include <mma.h>
#include <math.h>
#include <cstdint>

#define MAXN 50000
#define MAXE 1600000

using namespace nvcuda;

// ---------------- device scratch ------------------------------------------
__device__ __align__(16) __half2 g_h1h[MAXN * 32]; // layer1 h, fp16 [N,64]
__device__ __align__(16) float g_as1[MAXN * 8];
__device__ __align__(16) float g_ad1[MAXN * 8];
__device__ __align__(16) float g_h1p[MAXN * 64];   // layer1 out (bias+elu)
__device__ __align__(16) __half2 g_h2h[MAXN * 32]; // layer2 h, fp16
__device__ __align__(16) float g_as2[MAXN];
__device__ __align__(16) float g_ad2[MAXN];
__device__ __align__(16) __half g_wh[256 * 64];    // W1 fp16 [256][64]
__device__ int g_cnt [MAXN];
__device__ int g_cur [MAXN];
__device__ int g_offs[MAXN + 1];
__device__ int g_bsum[64];
__device__ __align__(16) int g_ebuf[MAXE];
__device__ int g_is64;

// ---------------- zero + edge dtype detect ---------------------------------
__global__ void zerodetect_kernel(const int* __restrict__ ei32, int E, int N) {
    int i = blockIdx.x * blockDim.x + threadIdx.x;
    if (i < N) { g_cnt[i] = 0; g_cur[i] = 0; }
    if (blockIdx.x == 0) {
        __shared__ int s_or;
        if (threadIdx.x == 0) s_or = 0;
        __syncthreads();
        int acc = 0;
        int nsamp = (E < 4096) ? E : 4096;
        for (int j = threadIdx.x; j < nsamp; j += blockDim.x)
            acc |= ei32[2 * j + 1];
        atomicOr(&s_or, acc);
        __syncthreads();
        if (threadIdx.x == 0) g_is64 = (s_or == 0) ? 1 : 0;
    }
}

// ---------------- W1 -> fp16 -------------------------------------------------
__global__ void wconv_kernel(const float* __restrict__ W1) {
    int i = blockIdx.x * blockDim.x + threadIdx.x;   // 16384
    g_wh[i] = __float2half_rn(W1[i]);
}

__global__ void count_kernel(const void* __restrict__ ei, int E, int N) {
    int i = blockIdx.x * blockDim.x + threadIdx.x;
    if (i >= E) return;
    int d = g_is64 ? (int)((const long long*)ei)[E + i]
                   : ((const int*)ei)[E + i];
    if ((unsigned)d < (unsigned)N) atomicAdd(&g_cnt[d], 1);
}

// ---------------- layer 1 GEMM via WMMA fp16 (HMMA) -------------------------
#define WS_LD 72
#define XS_LD 264
#define OS_LD 72
__global__ void __launch_bounds__(256) gemm1_wmma_kernel(
        const float* __restrict__ x,
        const float* __restrict__ att_s, const float* __restrict__ att_d,
        int N) {
    extern __shared__ char smem[];
    __half* Wsm = (__half*)smem;                     // [256][WS_LD]
    __half* xs  = (__half*)(smem + 36864);           // [128][XS_LD]
    float*  osm = (float*)(smem + 36864);            // aliases xs

    int tid = threadIdx.x;
    int wid = tid >> 5;
    int r0 = blockIdx.x * 128;

    #pragma unroll
    for (int i = 0; i < 8; i++) {
        int idx = tid + i * 256;
        int row = idx >> 3, q = idx & 7;
        *(uint4*)&Wsm[row * WS_LD + q * 8] = ((const uint4*)g_wh)[idx];
    }
    #pragma unroll
    for (int it = 0; it < 32; it++) {
        int idx = tid + it * 256;
        int row = idx >> 6, f4 = idx & 63;
        int grow = r0 + row;
        float4 v = make_float4(0.f, 0.f, 0.f, 0.f);
        if (grow < N) v = ((const float4*)x)[(size_t)grow * 64 + f4];
        __half2 h01 = __floats2half2_rn(v.x, v.y);
        __half2 h23 = __floats2half2_rn(v.z, v.w);
        *(uint2*)&xs[row * XS_LD + f4 * 4] =
            make_uint2(*(uint32_t*)&h01, *(uint32_t*)&h23);
    }
    __syncthreads();

    wmma::fragment<wmma::accumulator, 16, 16, 16, float> c[4];
    #pragma unroll
    for (int n = 0; n < 4; n++) wmma::fill_fragment(c[n], 0.f);

    #pragma unroll
    for (int k16 = 0; k16 < 16; k16++) {
        wmma::fragment<wmma::matrix_a, 16, 16, 16, __half, wmma::row_major> a;
        wmma::load_matrix_sync(a, &xs[wid * 16 * XS_LD + k16 * 16], XS_LD);
        #pragma unroll
        for (int n = 0; n < 4; n++) {
            wmma::fragment<wmma::matrix_b, 16, 16, 16, __half, wmma::row_major> b;
            wmma::load_matrix_sync(b, &Wsm[k16 * 16 * WS_LD + n * 16], WS_LD);
            wmma::mma_sync(c[n], a, b, c[n]);
        }
    }

    __syncthreads();
    #pragma unroll
    for (int n = 0; n < 4; n++)
        wmma::store_matrix_sync(&osm[wid * 16 * OS_LD + n * 16], c[n], OS_LD,
                                wmma::mem_row_major);
    __syncthreads();

    int row = tid >> 1, half = tid & 1;
    int grow = r0 + row;
    if (grow < N) {
        const float* orow = &osm[row * OS_LD + half * 32];
        #pragma unroll
        for (int q = 0; q < 4; q++) {
            __half2 hh[4];
            #pragma unroll
            for (int p = 0; p < 4; p++)
                hh[p] = __floats2half2_rn(orow[q * 8 + p * 2], orow[q * 8 + p * 2 + 1]);
            *(uint4*)(&g_h1h[(size_t)grow * 32 + half * 16 + q * 4]) = *(uint4*)hh;
        }
        #pragma unroll
        for (int hh = 0; hh < 4; hh++) {
            int h = half * 4 + hh;
            float as = 0.f, ad = 0.f;
            #pragma unroll
            for (int j = 0; j < 8; j++) {
                float cv = orow[hh * 8 + j];
                as = fmaf(cv, __ldg(&att_s[h * 8 + j]), as);
                ad = fmaf(cv, __ldg(&att_d[h * 8 + j]), ad);
            }
            g_as1[grow * 8 + h] = as;
            g_ad1[grow * 8 + h] = ad;
        }
    }
}

// ---------------- scan ------------------------------------------------------
__global__ void scan_block_kernel(int N) {
    __shared__ int wsum[32];
    int tid = threadIdx.x, lane = tid & 31, wid = tid >> 5;
    int i = blockIdx.x * 1024 + tid;
    int v = (i < N) ? g_cnt[i] : 0;
    int sc = v;
    #pragma unroll
    for (int o = 1; o < 32; o <<= 1) {
        int t = __shfl_up_sync(0xffffffffu, sc, o);
        if (lane >= o) sc += t;
    }
    if (lane == 31) wsum[wid] = sc;
    __syncthreads();
    if (wid == 0) {
        int s = wsum[lane];
        #pragma unroll
        for (int o = 1; o < 32; o <<= 1) {
            int t = __shfl_up_sync(0xffffffffu, s, o);
            if (lane >= o) s += t;
        }
        wsum[lane] = s;
    }
    __syncthreads();
    int add = (wid > 0) ? wsum[wid - 1] : 0;
    if (i < N) g_offs[i] = add + sc - v;
    if (tid == 0) g_bsum[blockIdx.x] = wsum[31];
}

__global__ void scan_add_kernel(int N, int nb) {
    __shared__ int prefix;
    int b = blockIdx.x;
    int lane = threadIdx.x & 31;
    if (threadIdx.x < 32) {
        int acc = 0;
        for (int j = lane; j < b; j += 32) acc += g_bsum[j];
        #pragma unroll
        for (int o = 16; o >= 1; o >>= 1) acc += __shfl_xor_sync(0xffffffffu, acc, o);
        if (lane == 0) prefix = acc;
    }
    __syncthreads();
    int i = b * 1024 + threadIdx.x;
    if (i < N) g_offs[i] += prefix;
    if (b == nb - 1 && threadIdx.x == 0) g_offs[N] = prefix + g_bsum[b];
}

__global__ void scatter_kernel(const void* __restrict__ ei, int E, int N) {
    int i = blockIdx.x * blockDim.x + threadIdx.x;
    if (i >= E) return;
    int s, d;
    if (g_is64) {
        const long long* e64 = (const long long*)ei;
        s = (int)e64[i]; d = (int)e64[E + i];
    } else {
        const int* e32 = (const int*)ei;
        s = e32[i]; d = e32[E + i];
    }
    if ((unsigned)d < (unsigned)N) {
        int p = atomicAdd(&g_cur[d], 1);
        g_ebuf[g_offs[d] + p] = s;
    }
}

// ---------------- agg helpers ------------------------------------------------
#define LRELU(e) ((e) > 0.f ? (e) : 0.2f * (e))

// ---------------- layer 1 aggregation ---------------------------------------
__global__ void agg1_kernel(const float* __restrict__ bias1, int N) {
    int warp = (blockIdx.x * blockDim.x + threadIdx.x) >> 5;
    int lane = threadIdx.x & 31;
    if (warp >= N) return;
    int dst = warp;
    int head = lane >> 2;
    float ad = g_ad1[dst * 8 + head];
    int beg = g_offs[dst], end = g_offs[dst + 1];

    float den = 0.f, ax = 0.f, ay = 0.f;
    int i = beg;
    for (; i < end && (i & 3); i++) {
        int s = __ldg(&g_ebuf[i]);
        float e = LRELU(__ldg(&g_as1[s * 8 + head]) + ad);
        float w = __expf(e);
        float2 hv = __half22float2(__ldg(&g_h1h[(size_t)s * 32 + lane]));
        den += w; ax = fmaf(w, hv.x, ax); ay = fmaf(w, hv.y, ay);
    }
    // 8-edge batches: two LDG.128 + 8 independent e-loads + 8 h-gathers
    for (; i + 8 <= end; i += 8) {
        int4 sa = *(const int4*)&g_ebuf[i];
        int4 sb = *(const int4*)&g_ebuf[i + 4];
        float e0 = __ldg(&g_as1[sa.x * 8 + head]);
        float e1 = __ldg(&g_as1[sa.y * 8 + head]);
        float e2 = __ldg(&g_as1[sa.z * 8 + head]);
        float e3 = __ldg(&g_as1[sa.w * 8 + head]);
        float e4 = __ldg(&g_as1[sb.x * 8 + head]);
        float e5 = __ldg(&g_as1[sb.y * 8 + head]);
        float e6 = __ldg(&g_as1[sb.z * 8 + head]);
        float e7 = __ldg(&g_as1[sb.w * 8 + head]);
        __half2 q0 = __ldg(&g_h1h[(size_t)sa.x * 32 + lane]);
        __half2 q1 = __ldg(&g_h1h[(size_t)sa.y * 32 + lane]);
        __half2 q2 = __ldg(&g_h1h[(size_t)sa.z * 32 + lane]);
        __half2 q3 = __ldg(&g_h1h[(size_t)sa.w * 32 + lane]);
        __half2 q4 = __ldg(&g_h1h[(size_t)sb.x * 32 + lane]);
        __half2 q5 = __ldg(&g_h1h[(size_t)sb.y * 32 + lane]);
        __half2 q6 = __ldg(&g_h1h[(size_t)sb.z * 32 + lane]);
        __half2 q7 = __ldg(&g_h1h[(size_t)sb.w * 32 + lane]);
        float w0 = __expf(LRELU(e0 + ad)), w1 = __expf(LRELU(e1 + ad));
        float w2 = __expf(LRELU(e2 + ad)), w3 = __expf(LRELU(e3 + ad));
        float w4 = __expf(LRELU(e4 + ad)), w5 = __expf(LRELU(e5 + ad));
        float w6 = __expf(LRELU(e6 + ad)), w7 = __expf(LRELU(e7 + ad));
        den += ((w0 + w1) + (w2 + w3)) + ((w4 + w5) + (w6 + w7));
        float2 f0 = __half22float2(q0), f1 = __half22float2(q1);
        float2 f2 = __half22float2(q2), f3 = __half22float2(q3);
        float2 f4 = __half22float2(q4), f5 = __half22float2(q5);
        float2 f6 = __half22float2(q6), f7 = __half22float2(q7);
        ax = fmaf(w0, f0.x, ax); ay = fmaf(w0, f0.y, ay);
        ax = fmaf(w1, f1.x, ax); ay = fmaf(w1, f1.y, ay);
        ax = fmaf(w2, f2.x, ax); ay = fmaf(w2, f2.y, ay);
        ax = fmaf(w3, f3.x, ax); ay = fmaf(w3, f3.y, ay);
        ax = fmaf(w4, f4.x, ax); ay = fmaf(w4, f4.y, ay);
        ax = fmaf(w5, f5.x, ax); ay = fmaf(w5, f5.y, ay);
        ax = fmaf(w6, f6.x, ax); ay = fmaf(w6, f6.y, ay);
        ax = fmaf(w7, f7.x, ax); ay = fmaf(w7, f7.y, ay);
    }
    for (; i + 4 <= end; i += 4) {
        int4 ss = *(const int4*)&g_ebuf[i];
        float e0 = __ldg(&g_as1[ss.x * 8 + head]);
        float e1 = __ldg(&g_as1[ss.y * 8 + head]);
        float e2 = __ldg(&g_as1[ss.z * 8 + head]);
        float e3 = __ldg(&g_as1[ss.w * 8 + head]);
        __half2 q0 = __ldg(&g_h1h[(size_t)ss.x * 32 + lane]);
        __half2 q1 = __ldg(&g_h1h[(size_t)ss.y * 32 + lane]);
        __half2 q2 = __ldg(&g_h1h[(size_t)ss.z * 32 + lane]);
        __half2 q3 = __ldg(&g_h1h[(size_t)ss.w * 32 + lane]);
        float w0 = __expf(LRELU(e0 + ad)), w1 = __expf(LRELU(e1 + ad));
        float w2 = __expf(LRELU(e2 + ad)), w3 = __expf(LRELU(e3 + ad));
        den += (w0 + w1) + (w2 + w3);
        float2 f0 = __half22float2(q0), f1 = __half22float2(q1);
        float2 f2 = __half22float2(q2), f3 = __half22float2(q3);
        ax = fmaf(w0, f0.x, ax); ay = fmaf(w0, f0.y, ay);
        ax = fmaf(w1, f1.x, ax); ay = fmaf(w1, f1.y, ay);
        ax = fmaf(w2, f2.x, ax); ay = fmaf(w2, f2.y, ay);
        ax = fmaf(w3, f3.x, ax); ay = fmaf(w3, f3.y, ay);
    }
    for (; i < end; i++) {
        int s = __ldg(&g_ebuf[i]);
        float e = LRELU(__ldg(&g_as1[s * 8 + head]) + ad);
        float w = __expf(e);
        float2 hv = __half22float2(__ldg(&g_h1h[(size_t)s * 32 + lane]));
        den += w; ax = fmaf(w, hv.x, ax); ay = fmaf(w, hv.y, ay);
    }
    float inv = 1.f / (den + 1e-16f);
    int c0 = lane * 2;
    float v0 = fmaf(ax, inv, bias1[c0]);
    float v1 = fmaf(ay, inv, bias1[c0 + 1]);
    v0 = (v0 > 0.f) ? v0 : expm1f(v0);
    v1 = (v1 > 0.f) ? v1 : expm1f(v1);
    ((float2*)g_h1p)[(size_t)dst * 32 + lane] = make_float2(v0, v1);
}

// ---------------- layer 2 GEMM ----------------------------------------------
__global__ void gemm2_kernel(const float* __restrict__ W2,
                             const float* __restrict__ att_s2, const float* __restrict__ att_d2,
                             int N) {
    __shared__ float Ws[64 * 64];
    __shared__ float xs[32 * 64];
    int tid = threadIdx.x;

    float4* Ws4 = (float4*)Ws;
    const float4* Wg4 = (const float4*)W2;
    #pragma unroll
    for (int i = 0; i < 4; i++) Ws4[tid + i * 256] = Wg4[tid + i * 256];

    int r0 = blockIdx.x * 32;
    float4* xs4 = (float4*)xs;
    const float4* xg4 = (const float4*)(g_h1p + (size_t)r0 * 64);
    int rows = N - r0; if (rows > 32) rows = 32;
    int nf4 = rows * 16;
    #pragma unroll
    for (int i = 0; i < 2; i++) {
        int idx = tid + i * 256;
        xs4[idx] = (idx < nf4) ? xg4[idx] : make_float4(0.f, 0.f, 0.f, 0.f);
    }
    __syncthreads();

    int r = tid >> 3, cg = tid & 7;
    float acc[8];
    #pragma unroll
    for (int j = 0; j < 8; j++) acc[j] = 0.f;
    const float* xr = xs + r * 64;
    #pragma unroll 8
    for (int k = 0; k < 64; k++) {
        float xv = xr[k];
        float4 w0 = Ws4[k * 16 + cg * 2];
        float4 w1 = Ws4[k * 16 + cg * 2 + 1];
        acc[0] = fmaf(xv, w0.x, acc[0]); acc[1] = fmaf(xv, w0.y, acc[1]);
        acc[2] = fmaf(xv, w0.z, acc[2]); acc[3] = fmaf(xv, w0.w, acc[3]);
        acc[4] = fmaf(xv, w1.x, acc[4]); acc[5] = fmaf(xv, w1.y, acc[5]);
        acc[6] = fmaf(xv, w1.z, acc[6]); acc[7] = fmaf(xv, w1.w, acc[7]);
    }

    float ps = 0.f, pd = 0.f;
    #pragma unroll
    for (int j = 0; j < 8; j++) {
        ps = fmaf(acc[j], att_s2[cg * 8 + j], ps);
        pd = fmaf(acc[j], att_d2[cg * 8 + j], pd);
    }
    #pragma unroll
    for (int o = 4; o >= 1; o >>= 1) {
        ps += __shfl_down_sync(0xffffffffu, ps, o);
        pd += __shfl_down_sync(0xffffffffu, pd, o);
    }

    int row = r0 + r;
    if (row < N) {
        __half2 hh[4];
        #pragma unroll
        for (int cp = 0; cp < 4; cp++)
            hh[cp] = __floats2half2_rn(acc[cp * 2], acc[cp * 2 + 1]);
        *(uint4*)(&g_h2h[(size_t)row * 32 + cg * 4]) = *(uint4*)hh;
        if (cg == 0) { g_as2[row] = ps; g_ad2[row] = pd; }
    }
}

// ---------------- layer 2 aggregation + log_softmax -------------------------
__global__ void agg2_kernel(const float* __restrict__ bias2, float* __restrict__ out, int N) {
    int warp = (blockIdx.x * blockDim.x + threadIdx.x) >> 5;
    int lane = threadIdx.x & 31;
    if (warp >= N) return;
    int dst = warp;
    float ad = g_ad2[dst];
    int beg = g_offs[dst], end = g_offs[dst + 1];

    float den = 0.f, ax = 0.f, ay = 0.f;
    int i = beg;
    for (; i < end && (i & 3); i++) {
        int s = __ldg(&g_ebuf[i]);
        float e = LRELU(__ldg(&g_as2[s]) + ad);
        float w = __expf(e);
        float2 hv = __half22float2(__ldg(&g_h2h[(size_t)s * 32 + lane]));
        den += w; ax = fmaf(w, hv.x, ax); ay = fmaf(w, hv.y, ay);
    }
    for (; i + 8 <= end; i += 8) {
        int4 sa = *(const int4*)&g_ebuf[i];
        int4 sb = *(const int4*)&g_ebuf[i + 4];
        float e0 = __ldg(&g_as2[sa.x]);
        float e1 = __ldg(&g_as2[sa.y]);
        float e2 = __ldg(&g_as2[sa.z]);
        float e3 = __ldg(&g_as2[sa.w]);
        float e4 = __ldg(&g_as2[sb.x]);
        float e5 = __ldg(&g_as2[sb.y]);
        float e6 = __ldg(&g_as2[sb.z]);
        float e7 = __ldg(&g_as2[sb.w]);
        __half2 q0 = __ldg(&g_h2h[(size_t)sa.x * 32 + lane]);
        __half2 q1 = __ldg(&g_h2h[(size_t)sa.y * 32 + lane]);
        __half2 q2 = __ldg(&g_h2h[(size_t)sa.z * 32 + lane]);
        __half2 q3 = __ldg(&g_h2h[(size_t)sa.w * 32 + lane]);
        __half2 q4 = __ldg(&g_h2h[(size_t)sb.x * 32 + lane]);
        __half2 q5 = __ldg(&g_h2h[(size_t)sb.y * 32 + lane]);
        __half2 q6 = __ldg(&g_h2h[(size_t)sb.z * 32 + lane]);
        __half2 q7 = __ldg(&g_h2h[(size_t)sb.w * 32 + lane]);
        float w0 = __expf(LRELU(e0 + ad)), w1 = __expf(LRELU(e1 + ad));
        float w2 = __expf(LRELU(e2 + ad)), w3 = __expf(LRELU(e3 + ad));
        float w4 = __expf(LRELU(e4 + ad)), w5 = __expf(LRELU(e5 + ad));
        float w6 = __expf(LRELU(e6 + ad)), w7 = __expf(LRELU(e7 + ad));
        den += ((w0 + w1) + (w2 + w3)) + ((w4 + w5) + (w6 + w7));
        float2 f0 = __half22float2(q0), f1 = __half22float2(q1);
        float2 f2 = __half22float2(q2), f3 = __half22float2(q3);
        float2 f4 = __half22float2(q4), f5 = __half22float2(q5);
        float2 f6 = __half22float2(q6), f7 = __half22float2(q7);
        ax = fmaf(w0, f0.x, ax); ay = fmaf(w0, f0.y, ay);
        ax = fmaf(w1, f1.x, ax); ay = fmaf(w1, f1.y, ay);
        ax = fmaf(w2, f2.x, ax); ay = fmaf(w2, f2.y, ay);
        ax = fmaf(w3, f3.x, ax); ay = fmaf(w3, f3.y, ay);
        ax = fmaf(w4, f4.x, ax); ay = fmaf(w4, f4.y, ay);
        ax = fmaf(w5, f5.x, ax); ay = fmaf(w5, f5.y, ay);
        ax = fmaf(w6, f6.x, ax); ay = fmaf(w6, f6.y, ay);
        ax = fmaf(w7, f7.x, ax); ay = fmaf(w7, f7.y, ay);
    }
    for (; i + 4 <= end; i += 4) {
        int4 ss = *(const int4*)&g_ebuf[i];
        float e0 = __ldg(&g_as2[ss.x]);
        float e1 = __ldg(&g_as2[ss.y]);
        float e2 = __ldg(&g_as2[ss.z]);
        float e3 = __ldg(&g_as2[ss.w]);
        __half2 q0 = __ldg(&g_h2h[(size_t)ss.x * 32 + lane]);
        __half2 q1 = __ldg(&g_h2h[(size_t)ss.y * 32 + lane]);
        __half2 q2 = __ldg(&g_h2h[(size_t)ss.z * 32 + lane]);
        __half2 q3 = __ldg(&g_h2h[(size_t)ss.w * 32 + lane]);
        float w0 = __expf(LRELU(e0 + ad)), w1 = __expf(LRELU(e1 + ad));
        float w2 = __expf(LRELU(e2 + ad)), w3 = __expf(LRELU(e3 + ad));
        den += (w0 + w1) + (w2 + w3);
        float2 f0 = __half22float2(q0), f1 = __half22float2(q1);
        float2 f2 = __half22float2(q2), f3 = __half22float2(q3);
        ax = fmaf(w0, f0.x, ax); ay = fmaf(w0, f0.y, ay);
        ax = fmaf(w1, f1.x, ax); ay = fmaf(w1, f1.y, ay);
        ax = fmaf(w2, f2.x, ax); ay = fmaf(w2, f2.y, ay);
        ax = fmaf(w3, f3.x, ax); ay = fmaf(w3, f3.y, ay);
    }
    for (; i < end; i++) {
        int s = __ldg(&g_ebuf[i]);
        float e = LRELU(__ldg(&g_as2[s]) + ad);
        float w = __expf(e);
        float2 hv = __half22float2(__ldg(&g_h2h[(size_t)s * 32 + lane]));
        den += w; ax = fmaf(w, hv.x, ax); ay = fmaf(w, hv.y, ay);
    }
    float inv = 1.f / (den + 1e-16f);
    int c0 = lane * 2;
    float v0 = fmaf(ax, inv, bias2[c0]);
    float v1 = fmaf(ay, inv, bias2[c0 + 1]);

    float m = fmaxf(v0, v1);
    #pragma unroll
    for (int o = 16; o >= 1; o >>= 1) m = fmaxf(m, __shfl_xor_sync(0xffffffffu, m, o));
    float se = __expf(v0 - m) + __expf(v1 - m);
    #pragma unroll
    for (int o = 16; o >= 1; o >>= 1) se += __shfl_xor_sync(0xffffffffu, se, o);
    float lse = m + logf(se);

    ((float2*)out)[(size_t)dst * 32 + lane] = make_float2(v0 - lse, v1 - lse);
}

// ---------------- launch ----------------------------------------------------
extern "C" void kernel_launch(void* const* d_in, const int* in_sizes, int n_in,
                              void* d_out, int out_size) {
    const float* x      = (const float*)d_in[0];
    const void*  ei     = d_in[1];
    const float* W1     = (const float*)d_in[2];
    const float* atts1  = (const float*)d_in[3];
    const float* attd1  = (const float*)d_in[4];
    const float* bias1  = (const float*)d_in[5];
    const float* W2     = (const float*)d_in[6];
    const float* atts2  = (const float*)d_in[7];
    const float* attd2  = (const float*)d_in[8];
    const float* bias2  = (const float*)d_in[9];
    float* out = (float*)d_out;

    int N = in_sizes[0] / 256;
    int E = in_sizes[1] / 2;
    int nb = (N + 1023) / 1024;

    // one-time handles (created on the first, non-captured, correctness call;
    // the captured work below is identical on every call)
    static cudaStream_t s2 = nullptr;
    static cudaEvent_t evRoot = nullptr, evG = nullptr;
    if (s2 == nullptr) {
        cudaStreamCreateWithFlags(&s2, cudaStreamNonBlocking);
        cudaEventCreateWithFlags(&evRoot, cudaEventDisableTiming);
        cudaEventCreateWithFlags(&evG, cudaEventDisableTiming);
        cudaFuncSetAttribute(gemm1_wmma_kernel,
                             cudaFuncAttributeMaxDynamicSharedMemorySize, 104448);
    }

    // fork: GEMM chain on s2, CSR chain on the main stream
    cudaEventRecord(evRoot, 0);
    cudaStreamWaitEvent(s2, evRoot, 0);

    wconv_kernel     <<<64, 256, 0, s2>>>(W1);
    gemm1_wmma_kernel<<<(N + 127) / 128, 256, 104448, s2>>>(x, atts1, attd1, N);
    cudaEventRecord(evG, s2);

    zerodetect_kernel<<<(N + 255) / 256, 256>>>((const int*)ei, E, N);
    count_kernel     <<<(E + 255) / 256, 256>>>(ei, E, N);
    scan_block_kernel<<<nb, 1024>>>(N);
    scan_add_kernel  <<<nb, 1024>>>(N, nb);
    scatter_kernel   <<<(E + 255) / 256, 256>>>(ei, E, N);

    // join: agg1 needs both chains
    cudaStreamWaitEvent(0, evG, 0);
    agg1_kernel <<<(N + 7) / 8, 256>>>(bias1, N);
    gemm2_kernel<<<(N + 31) / 32, 256>>>(W2, atts2, attd2, N);
    agg2_kernel <<<(N + 7) / 8, 256>>>(bias2, out, N);
}

// round 12
// speedup vs baseline: 1.0062x; 1.0062x over previous
#include <cuda_runtime.h>
#include <cuda_fp16.h>
#include <mma.h>
#include <math.h>
#include <cstdint>

#define MAXN 50000
#define MAXE 1600000

using namespace nvcuda;

// ---------------- device scratch ------------------------------------------
__device__ __align__(16) __half2 g_h1h[MAXN * 32]; // layer1 h, fp16 [N,64]
__device__ __align__(16) float g_as1[MAXN * 8];
__device__ __align__(16) float g_ad1[MAXN * 8];
__device__ __align__(16) float g_h1p[MAXN * 64];   // layer1 out (bias+elu)
__device__ __align__(16) __half2 g_h2h[MAXN * 32]; // layer2 h, fp16
__device__ __align__(16) float g_as2[MAXN];
__device__ __align__(16) float g_ad2[MAXN];
__device__ __align__(16) __half g_wh[256 * 64];    // W1 fp16 [256][64]
__device__ int g_cnt [MAXN];
__device__ int g_cur [MAXN];
__device__ int g_offs[MAXN + 1];
__device__ int g_bsum[64];
__device__ __align__(16) int g_ebuf[MAXE];
__device__ int g_is64;

// ---------------- zero + edge dtype detect ---------------------------------
__global__ void zerodetect_kernel(const int* __restrict__ ei32, int E, int N) {
    int i = blockIdx.x * blockDim.x + threadIdx.x;
    if (i < N) { g_cnt[i] = 0; g_cur[i] = 0; }
    if (blockIdx.x == 0) {
        __shared__ int s_or;
        if (threadIdx.x == 0) s_or = 0;
        __syncthreads();
        int acc = 0;
        int nsamp = (E < 4096) ? E : 4096;
        for (int j = threadIdx.x; j < nsamp; j += blockDim.x)
            acc |= ei32[2 * j + 1];
        atomicOr(&s_or, acc);
        __syncthreads();
        if (threadIdx.x == 0) g_is64 = (s_or == 0) ? 1 : 0;
    }
}

// ---------------- W1 -> fp16 -------------------------------------------------
__global__ void wconv_kernel(const float* __restrict__ W1) {
    int i = blockIdx.x * blockDim.x + threadIdx.x;   // 16384
    g_wh[i] = __float2half_rn(W1[i]);
}

__global__ void count_kernel(const void* __restrict__ ei, int E, int N) {
    int i = blockIdx.x * blockDim.x + threadIdx.x;
    if (i >= E) return;
    int d = g_is64 ? (int)((const long long*)ei)[E + i]
                   : ((const int*)ei)[E + i];
    if ((unsigned)d < (unsigned)N) atomicAdd(&g_cnt[d], 1);
}

// ---------------- layer 1 GEMM via WMMA fp16 (HMMA) -------------------------
#define WS_LD 72
#define XS_LD 264
#define OS_LD 72
__global__ void __launch_bounds__(256) gemm1_wmma_kernel(
        const float* __restrict__ x,
        const float* __restrict__ att_s, const float* __restrict__ att_d,
        int N) {
    extern __shared__ char smem[];
    __half* Wsm = (__half*)smem;                     // [256][WS_LD]
    __half* xs  = (__half*)(smem + 36864);           // [128][XS_LD]
    float*  osm = (float*)(smem + 36864);            // aliases xs

    int tid = threadIdx.x;
    int wid = tid >> 5;
    int r0 = blockIdx.x * 128;

    #pragma unroll
    for (int i = 0; i < 8; i++) {
        int idx = tid + i * 256;
        int row = idx >> 3, q = idx & 7;
        *(uint4*)&Wsm[row * WS_LD + q * 8] = ((const uint4*)g_wh)[idx];
    }
    #pragma unroll
    for (int it = 0; it < 32; it++) {
        int idx = tid + it * 256;
        int row = idx >> 6, f4 = idx & 63;
        int grow = r0 + row;
        float4 v = make_float4(0.f, 0.f, 0.f, 0.f);
        if (grow < N) v = ((const float4*)x)[(size_t)grow * 64 + f4];
        __half2 h01 = __floats2half2_rn(v.x, v.y);
        __half2 h23 = __floats2half2_rn(v.z, v.w);
        *(uint2*)&xs[row * XS_LD + f4 * 4] =
            make_uint2(*(uint32_t*)&h01, *(uint32_t*)&h23);
    }
    __syncthreads();

    wmma::fragment<wmma::accumulator, 16, 16, 16, float> c[4];
    #pragma unroll
    for (int n = 0; n < 4; n++) wmma::fill_fragment(c[n], 0.f);

    #pragma unroll
    for (int k16 = 0; k16 < 16; k16++) {
        wmma::fragment<wmma::matrix_a, 16, 16, 16, __half, wmma::row_major> a;
        wmma::load_matrix_sync(a, &xs[wid * 16 * XS_LD + k16 * 16], XS_LD);
        #pragma unroll
        for (int n = 0; n < 4; n++) {
            wmma::fragment<wmma::matrix_b, 16, 16, 16, __half, wmma::row_major> b;
            wmma::load_matrix_sync(b, &Wsm[k16 * 16 * WS_LD + n * 16], WS_LD);
            wmma::mma_sync(c[n], a, b, c[n]);
        }
    }

    __syncthreads();
    #pragma unroll
    for (int n = 0; n < 4; n++)
        wmma::store_matrix_sync(&osm[wid * 16 * OS_LD + n * 16], c[n], OS_LD,
                                wmma::mem_row_major);
    __syncthreads();

    int row = tid >> 1, half = tid & 1;
    int grow = r0 + row;
    if (grow < N) {
        const float* orow = &osm[row * OS_LD + half * 32];
        #pragma unroll
        for (int q = 0; q < 4; q++) {
            __half2 hh[4];
            #pragma unroll
            for (int p = 0; p < 4; p++)
                hh[p] = __floats2half2_rn(orow[q * 8 + p * 2], orow[q * 8 + p * 2 + 1]);
            *(uint4*)(&g_h1h[(size_t)grow * 32 + half * 16 + q * 4]) = *(uint4*)hh;
        }
        #pragma unroll
        for (int hh = 0; hh < 4; hh++) {
            int h = half * 4 + hh;
            float as = 0.f, ad = 0.f;
            #pragma unroll
            for (int j = 0; j < 8; j++) {
                float cv = orow[hh * 8 + j];
                as = fmaf(cv, __ldg(&att_s[h * 8 + j]), as);
                ad = fmaf(cv, __ldg(&att_d[h * 8 + j]), ad);
            }
            g_as1[grow * 8 + h] = as;
            g_ad1[grow * 8 + h] = ad;
        }
    }
}

// ---------------- scan ------------------------------------------------------
__global__ void scan_block_kernel(int N) {
    __shared__ int wsum[32];
    int tid = threadIdx.x, lane = tid & 31, wid = tid >> 5;
    int i = blockIdx.x * 1024 + tid;
    int v = (i < N) ? g_cnt[i] : 0;
    int sc = v;
    #pragma unroll
    for (int o = 1; o < 32; o <<= 1) {
        int t = __shfl_up_sync(0xffffffffu, sc, o);
        if (lane >= o) sc += t;
    }
    if (lane == 31) wsum[wid] = sc;
    __syncthreads();
    if (wid == 0) {
        int s = wsum[lane];
        #pragma unroll
        for (int o = 1; o < 32; o <<= 1) {
            int t = __shfl_up_sync(0xffffffffu, s, o);
            if (lane >= o) s += t;
        }
        wsum[lane] = s;
    }
    __syncthreads();
    int add = (wid > 0) ? wsum[wid - 1] : 0;
    if (i < N) g_offs[i] = add + sc - v;
    if (tid == 0) g_bsum[blockIdx.x] = wsum[31];
}

__global__ void scan_add_kernel(int N, int nb) {
    __shared__ int prefix;
    int b = blockIdx.x;
    int lane = threadIdx.x & 31;
    if (threadIdx.x < 32) {
        int acc = 0;
        for (int j = lane; j < b; j += 32) acc += g_bsum[j];
        #pragma unroll
        for (int o = 16; o >= 1; o >>= 1) acc += __shfl_xor_sync(0xffffffffu, acc, o);
        if (lane == 0) prefix = acc;
    }
    __syncthreads();
    int i = b * 1024 + threadIdx.x;
    if (i < N) g_offs[i] += prefix;
    if (b == nb - 1 && threadIdx.x == 0) g_offs[N] = prefix + g_bsum[b];
}

__global__ void scatter_kernel(const void* __restrict__ ei, int E, int N) {
    int i = blockIdx.x * blockDim.x + threadIdx.x;
    if (i >= E) return;
    int s, d;
    if (g_is64) {
        const long long* e64 = (const long long*)ei;
        s = (int)e64[i]; d = (int)e64[E + i];
    } else {
        const int* e32 = (const int*)ei;
        s = e32[i]; d = e32[E + i];
    }
    if ((unsigned)d < (unsigned)N) {
        int p = atomicAdd(&g_cur[d], 1);
        g_ebuf[g_offs[d] + p] = s;
    }
}

// ---------------- agg helpers ------------------------------------------------
#define LRELU(e) ((e) > 0.f ? (e) : 0.2f * (e))

// ---------------- layer 1 aggregation ---------------------------------------
__global__ void agg1_kernel(const float* __restrict__ bias1, int N) {
    int warp = (blockIdx.x * blockDim.x + threadIdx.x) >> 5;
    int lane = threadIdx.x & 31;
    if (warp >= N) return;
    int dst = warp;
    int head = lane >> 2;
    float ad = g_ad1[dst * 8 + head];
    int beg = g_offs[dst], end = g_offs[dst + 1];

    float den = 0.f, ax = 0.f, ay = 0.f;
    int i = beg;
    for (; i < end && (i & 3); i++) {
        int s = __ldg(&g_ebuf[i]);
        float e = LRELU(__ldg(&g_as1[s * 8 + head]) + ad);
        float w = __expf(e);
        float2 hv = __half22float2(__ldg(&g_h1h[(size_t)s * 32 + lane]));
        den += w; ax = fmaf(w, hv.x, ax); ay = fmaf(w, hv.y, ay);
    }
    // 8-edge batches: two LDG.128 + 8 independent e-loads + 8 h-gathers
    for (; i + 8 <= end; i += 8) {
        int4 sa = *(const int4*)&g_ebuf[i];
        int4 sb = *(const int4*)&g_ebuf[i + 4];
        float e0 = __ldg(&g_as1[sa.x * 8 + head]);
        float e1 = __ldg(&g_as1[sa.y * 8 + head]);
        float e2 = __ldg(&g_as1[sa.z * 8 + head]);
        float e3 = __ldg(&g_as1[sa.w * 8 + head]);
        float e4 = __ldg(&g_as1[sb.x * 8 + head]);
        float e5 = __ldg(&g_as1[sb.y * 8 + head]);
        float e6 = __ldg(&g_as1[sb.z * 8 + head]);
        float e7 = __ldg(&g_as1[sb.w * 8 + head]);
        __half2 q0 = __ldg(&g_h1h[(size_t)sa.x * 32 + lane]);
        __half2 q1 = __ldg(&g_h1h[(size_t)sa.y * 32 + lane]);
        __half2 q2 = __ldg(&g_h1h[(size_t)sa.z * 32 + lane]);
        __half2 q3 = __ldg(&g_h1h[(size_t)sa.w * 32 + lane]);
        __half2 q4 = __ldg(&g_h1h[(size_t)sb.x * 32 + lane]);
        __half2 q5 = __ldg(&g_h1h[(size_t)sb.y * 32 + lane]);
        __half2 q6 = __ldg(&g_h1h[(size_t)sb.z * 32 + lane]);
        __half2 q7 = __ldg(&g_h1h[(size_t)sb.w * 32 + lane]);
        float w0 = __expf(LRELU(e0 + ad)), w1 = __expf(LRELU(e1 + ad));
        float w2 = __expf(LRELU(e2 + ad)), w3 = __expf(LRELU(e3 + ad));
        float w4 = __expf(LRELU(e4 + ad)), w5 = __expf(LRELU(e5 + ad));
        float w6 = __expf(LRELU(e6 + ad)), w7 = __expf(LRELU(e7 + ad));
        den += ((w0 + w1) + (w2 + w3)) + ((w4 + w5) + (w6 + w7));
        float2 f0 = __half22float2(q0), f1 = __half22float2(q1);
        float2 f2 = __half22float2(q2), f3 = __half22float2(q3);
        float2 f4 = __half22float2(q4), f5 = __half22float2(q5);
        float2 f6 = __half22float2(q6), f7 = __half22float2(q7);
        ax = fmaf(w0, f0.x, ax); ay = fmaf(w0, f0.y, ay);
        ax = fmaf(w1, f1.x, ax); ay = fmaf(w1, f1.y, ay);
        ax = fmaf(w2, f2.x, ax); ay = fmaf(w2, f2.y, ay);
        ax = fmaf(w3, f3.x, ax); ay = fmaf(w3, f3.y, ay);
        ax = fmaf(w4, f4.x, ax); ay = fmaf(w4, f4.y, ay);
        ax = fmaf(w5, f5.x, ax); ay = fmaf(w5, f5.y, ay);
        ax = fmaf(w6, f6.x, ax); ay = fmaf(w6, f6.y, ay);
        ax = fmaf(w7, f7.x, ax); ay = fmaf(w7, f7.y, ay);
    }
    for (; i + 4 <= end; i += 4) {
        int4 ss = *(const int4*)&g_ebuf[i];
        float e0 = __ldg(&g_as1[ss.x * 8 + head]);
        float e1 = __ldg(&g_as1[ss.y * 8 + head]);
        float e2 = __ldg(&g_as1[ss.z * 8 + head]);
        float e3 = __ldg(&g_as1[ss.w * 8 + head]);
        __half2 q0 = __ldg(&g_h1h[(size_t)ss.x * 32 + lane]);
        __half2 q1 = __ldg(&g_h1h[(size_t)ss.y * 32 + lane]);
        __half2 q2 = __ldg(&g_h1h[(size_t)ss.z * 32 + lane]);
        __half2 q3 = __ldg(&g_h1h[(size_t)ss.w * 32 + lane]);
        float w0 = __expf(LRELU(e0 + ad)), w1 = __expf(LRELU(e1 + ad));
        float w2 = __expf(LRELU(e2 + ad)), w3 = __expf(LRELU(e3 + ad));
        den += (w0 + w1) + (w2 + w3);
        float2 f0 = __half22float2(q0), f1 = __half22float2(q1);
        float2 f2 = __half22float2(q2), f3 = __half22float2(q3);
        ax = fmaf(w0, f0.x, ax); ay = fmaf(w0, f0.y, ay);
        ax = fmaf(w1, f1.x, ax); ay = fmaf(w1, f1.y, ay);
        ax = fmaf(w2, f2.x, ax); ay = fmaf(w2, f2.y, ay);
        ax = fmaf(w3, f3.x, ax); ay = fmaf(w3, f3.y, ay);
    }
    for (; i < end; i++) {
        int s = __ldg(&g_ebuf[i]);
        float e = LRELU(__ldg(&g_as1[s * 8 + head]) + ad);
        float w = __expf(e);
        float2 hv = __half22float2(__ldg(&g_h1h[(size_t)s * 32 + lane]));
        den += w; ax = fmaf(w, hv.x, ax); ay = fmaf(w, hv.y, ay);
    }
    float inv = 1.f / (den + 1e-16f);
    int c0 = lane * 2;
    float v0 = fmaf(ax, inv, bias1[c0]);
    float v1 = fmaf(ay, inv, bias1[c0 + 1]);
    v0 = (v0 > 0.f) ? v0 : expm1f(v0);
    v1 = (v1 > 0.f) ? v1 : expm1f(v1);
    ((float2*)g_h1p)[(size_t)dst * 32 + lane] = make_float2(v0, v1);
}

// ---------------- layer 2 GEMM ----------------------------------------------
__global__ void gemm2_kernel(const float* __restrict__ W2,
                             const float* __restrict__ att_s2, const float* __restrict__ att_d2,
                             int N) {
    __shared__ float Ws[64 * 64];
    __shared__ float xs[32 * 64];
    int tid = threadIdx.x;

    float4* Ws4 = (float4*)Ws;
    const float4* Wg4 = (const float4*)W2;
    #pragma unroll
    for (int i = 0; i < 4; i++) Ws4[tid + i * 256] = Wg4[tid + i * 256];

    int r0 = blockIdx.x * 32;
    float4* xs4 = (float4*)xs;
    const float4* xg4 = (const float4*)(g_h1p + (size_t)r0 * 64);
    int rows = N - r0; if (rows > 32) rows = 32;
    int nf4 = rows * 16;
    #pragma unroll
    for (int i = 0; i < 2; i++) {
        int idx = tid + i * 256;
        xs4[idx] = (idx < nf4) ? xg4[idx] : make_float4(0.f, 0.f, 0.f, 0.f);
    }
    __syncthreads();

    int r = tid >> 3, cg = tid & 7;
    float acc[8];
    #pragma unroll
    for (int j = 0; j < 8; j++) acc[j] = 0.f;
    const float* xr = xs + r * 64;
    #pragma unroll 8
    for (int k = 0; k < 64; k++) {
        float xv = xr[k];
        float4 w0 = Ws4[k * 16 + cg * 2];
        float4 w1 = Ws4[k * 16 + cg * 2 + 1];
        acc[0] = fmaf(xv, w0.x, acc[0]); acc[1] = fmaf(xv, w0.y, acc[1]);
        acc[2] = fmaf(xv, w0.z, acc[2]); acc[3] = fmaf(xv, w0.w, acc[3]);
        acc[4] = fmaf(xv, w1.x, acc[4]); acc[5] = fmaf(xv, w1.y, acc[5]);
        acc[6] = fmaf(xv, w1.z, acc[6]); acc[7] = fmaf(xv, w1.w, acc[7]);
    }

    float ps = 0.f, pd = 0.f;
    #pragma unroll
    for (int j = 0; j < 8; j++) {
        ps = fmaf(acc[j], att_s2[cg * 8 + j], ps);
        pd = fmaf(acc[j], att_d2[cg * 8 + j], pd);
    }
    #pragma unroll
    for (int o = 4; o >= 1; o >>= 1) {
        ps += __shfl_down_sync(0xffffffffu, ps, o);
        pd += __shfl_down_sync(0xffffffffu, pd, o);
    }

    int row = r0 + r;
    if (row < N) {
        __half2 hh[4];
        #pragma unroll
        for (int cp = 0; cp < 4; cp++)
            hh[cp] = __floats2half2_rn(acc[cp * 2], acc[cp * 2 + 1]);
        *(uint4*)(&g_h2h[(size_t)row * 32 + cg * 4]) = *(uint4*)hh;
        if (cg == 0) { g_as2[row] = ps; g_ad2[row] = pd; }
    }
}

// ---------------- layer 2 aggregation + log_softmax -------------------------
__global__ void agg2_kernel(const float* __restrict__ bias2, float* __restrict__ out, int N) {
    int warp = (blockIdx.x * blockDim.x + threadIdx.x) >> 5;
    int lane = threadIdx.x & 31;
    if (warp >= N) return;
    int dst = warp;
    float ad = g_ad2[dst];
    int beg = g_offs[dst], end = g_offs[dst + 1];

    float den = 0.f, ax = 0.f, ay = 0.f;
    int i = beg;
    for (; i < end && (i & 3); i++) {
        int s = __ldg(&g_ebuf[i]);
        float e = LRELU(__ldg(&g_as2[s]) + ad);
        float w = __expf(e);
        float2 hv = __half22float2(__ldg(&g_h2h[(size_t)s * 32 + lane]));
        den += w; ax = fmaf(w, hv.x, ax); ay = fmaf(w, hv.y, ay);
    }
    for (; i + 8 <= end; i += 8) {
        int4 sa = *(const int4*)&g_ebuf[i];
        int4 sb = *(const int4*)&g_ebuf[i + 4];
        float e0 = __ldg(&g_as2[sa.x]);
        float e1 = __ldg(&g_as2[sa.y]);
        float e2 = __ldg(&g_as2[sa.z]);
        float e3 = __ldg(&g_as2[sa.w]);
        float e4 = __ldg(&g_as2[sb.x]);
        float e5 = __ldg(&g_as2[sb.y]);
        float e6 = __ldg(&g_as2[sb.z]);
        float e7 = __ldg(&g_as2[sb.w]);
        __half2 q0 = __ldg(&g_h2h[(size_t)sa.x * 32 + lane]);
        __half2 q1 = __ldg(&g_h2h[(size_t)sa.y * 32 + lane]);
        __half2 q2 = __ldg(&g_h2h[(size_t)sa.z * 32 + lane]);
        __half2 q3 = __ldg(&g_h2h[(size_t)sa.w * 32 + lane]);
        __half2 q4 = __ldg(&g_h2h[(size_t)sb.x * 32 + lane]);
        __half2 q5 = __ldg(&g_h2h[(size_t)sb.y * 32 + lane]);
        __half2 q6 = __ldg(&g_h2h[(size_t)sb.z * 32 + lane]);
        __half2 q7 = __ldg(&g_h2h[(size_t)sb.w * 32 + lane]);
        float w0 = __expf(LRELU(e0 + ad)), w1 = __expf(LRELU(e1 + ad));
        float w2 = __expf(LRELU(e2 + ad)), w3 = __expf(LRELU(e3 + ad));
        float w4 = __expf(LRELU(e4 + ad)), w5 = __expf(LRELU(e5 + ad));
        float w6 = __expf(LRELU(e6 + ad)), w7 = __expf(LRELU(e7 + ad));
        den += ((w0 + w1) + (w2 + w3)) + ((w4 + w5) + (w6 + w7));
        float2 f0 = __half22float2(q0), f1 = __half22float2(q1);
        float2 f2 = __half22float2(q2), f3 = __half22float2(q3);
        float2 f4 = __half22float2(q4), f5 = __half22float2(q5);
        float2 f6 = __half22float2(q6), f7 = __half22float2(q7);
        ax = fmaf(w0, f0.x, ax); ay = fmaf(w0, f0.y, ay);
        ax = fmaf(w1, f1.x, ax); ay = fmaf(w1, f1.y, ay);
        ax = fmaf(w2, f2.x, ax); ay = fmaf(w2, f2.y, ay);
        ax = fmaf(w3, f3.x, ax); ay = fmaf(w3, f3.y, ay);
        ax = fmaf(w4, f4.x, ax); ay = fmaf(w4, f4.y, ay);
        ax = fmaf(w5, f5.x, ax); ay = fmaf(w5, f5.y, ay);
        ax = fmaf(w6, f6.x, ax); ay = fmaf(w6, f6.y, ay);
        ax = fmaf(w7, f7.x, ax); ay = fmaf(w7, f7.y, ay);
    }
    for (; i + 4 <= end; i += 4) {
        int4 ss = *(const int4*)&g_ebuf[i];
        float e0 = __ldg(&g_as2[ss.x]);
        float e1 = __ldg(&g_as2[ss.y]);
        float e2 = __ldg(&g_as2[ss.z]);
        float e3 = __ldg(&g_as2[ss.w]);
        __half2 q0 = __ldg(&g_h2h[(size_t)ss.x * 32 + lane]);
        __half2 q1 = __ldg(&g_h2h[(size_t)ss.y * 32 + lane]);
        __half2 q2 = __ldg(&g_h2h[(size_t)ss.z * 32 + lane]);
        __half2 q3 = __ldg(&g_h2h[(size_t)ss.w * 32 + lane]);
        float w0 = __expf(LRELU(e0 + ad)), w1 = __expf(LRELU(e1 + ad));
        float w2 = __expf(LRELU(e2 + ad)), w3 = __expf(LRELU(e3 + ad));
        den += (w0 + w1) + (w2 + w3);
        float2 f0 = __half22float2(q0), f1 = __half22float2(q1);
        float2 f2 = __half22float2(q2), f3 = __half22float2(q3);
        ax = fmaf(w0, f0.x, ax); ay = fmaf(w0, f0.y, ay);
        ax = fmaf(w1, f1.x, ax); ay = fmaf(w1, f1.y, ay);
        ax = fmaf(w2, f2.x, ax); ay = fmaf(w2, f2.y, ay);
        ax = fmaf(w3, f3.x, ax); ay = fmaf(w3, f3.y, ay);
    }
    for (; i < end; i++) {
        int s = __ldg(&g_ebuf[i]);
        float e = LRELU(__ldg(&g_as2[s]) + ad);
        float w = __expf(e);
        float2 hv = __half22float2(__ldg(&g_h2h[(size_t)s * 32 + lane]));
        den += w; ax = fmaf(w, hv.x, ax); ay = fmaf(w, hv.y, ay);
    }
    float inv = 1.f / (den + 1e-16f);
    int c0 = lane * 2;
    float v0 = fmaf(ax, inv, bias2[c0]);
    float v1 = fmaf(ay, inv, bias2[c0 + 1]);

    float m = fmaxf(v0, v1);
    #pragma unroll
    for (int o = 16; o >= 1; o >>= 1) m = fmaxf(m, __shfl_xor_sync(0xffffffffu, m, o));
    float se = __expf(v0 - m) + __expf(v1 - m);
    #pragma unroll
    for (int o = 16; o >= 1; o >>= 1) se += __shfl_xor_sync(0xffffffffu, se, o);
    float lse = m + logf(se);

    ((float2*)out)[(size_t)dst * 32 + lane] = make_float2(v0 - lse, v1 - lse);
}

// ---------------- launch ----------------------------------------------------
extern "C" void kernel_launch(void* const* d_in, const int* in_sizes, int n_in,
                              void* d_out, int out_size) {
    const float* x      = (const float*)d_in[0];
    const void*  ei     = d_in[1];
    const float* W1     = (const float*)d_in[2];
    const float* atts1  = (const float*)d_in[3];
    const float* attd1  = (const float*)d_in[4];
    const float* bias1  = (const float*)d_in[5];
    const float* W2     = (const float*)d_in[6];
    const float* atts2  = (const float*)d_in[7];
    const float* attd2  = (const float*)d_in[8];
    const float* bias2  = (const float*)d_in[9];
    float* out = (float*)d_out;

    int N = in_sizes[0] / 256;
    int E = in_sizes[1] / 2;
    int nb = (N + 1023) / 1024;

    // one-time handles (created on the first, non-captured, correctness call;
    // the captured work below is identical on every call)
    static cudaStream_t s2 = nullptr;
    static cudaEvent_t evRoot = nullptr, evG = nullptr;
    if (s2 == nullptr) {
        cudaStreamCreateWithFlags(&s2, cudaStreamNonBlocking);
        cudaEventCreateWithFlags(&evRoot, cudaEventDisableTiming);
        cudaEventCreateWithFlags(&evG, cudaEventDisableTiming);
        cudaFuncSetAttribute(gemm1_wmma_kernel,
                             cudaFuncAttributeMaxDynamicSharedMemorySize, 104448);
    }

    // fork: GEMM chain on s2, CSR chain on the main stream
    cudaEventRecord(evRoot, 0);
    cudaStreamWaitEvent(s2, evRoot, 0);

    wconv_kernel     <<<64, 256, 0, s2>>>(W1);
    gemm1_wmma_kernel<<<(N + 127) / 128, 256, 104448, s2>>>(x, atts1, attd1, N);
    cudaEventRecord(evG, s2);

    zerodetect_kernel<<<(N + 255) / 256, 256>>>((const int*)ei, E, N);
    count_kernel     <<<(E + 255) / 256, 256>>>(ei, E, N);
    scan_block_kernel<<<nb, 1024>>>(N);
    scan_add_kernel  <<<nb, 1024>>>(N, nb);
    scatter_kernel   <<<(E + 255) / 256, 256>>>(ei, E, N);

    // join: agg1 needs both chains
    cudaStreamWaitEvent(0, evG, 0);
    agg1_kernel <<<(N + 7) / 8, 256>>>(bias1, N);
    gemm2_kernel<<<(N + 31) / 32, 256>>>(W2, atts2, attd2, N);
    agg2_kernel <<<(N + 7) / 8, 256>>>(bias2, out, N);
}